// round 5
// baseline (speedup 1.0000x reference)
#include <cuda_runtime.h>

// Problem constants (fixed by setup_inputs: img [1,1,544,960], T=8, R=4)
#define H  544
#define W  960
#define T  8
#define R  4
#define HB (H/T)                  // 68
#define WB (W/T)                  // 120
#define NB (HB*WB)                // 8160
#define NC ((2*R+1)*(2*R+1))      // 81
#define WIN (T + 2*R)             // 16

// ---------------- scratch (device globals) ----------------------------------
__device__ float         g_cur_blur[H*W];
__device__ unsigned char g_cur_q[H*W];
__device__ unsigned char g_prev_q[H*W];
__device__ char2         g_vec[NB];     // (vy, vx) = (-dy, -dx)

// spiral rank LUT (row-major over (dy+R, dx+R)), precomputed for R=4
__constant__ unsigned char c_spiral[NC] = {
    74, 73, 72, 71, 70, 69, 68, 67, 66,
    75, 44, 43, 42, 41, 40, 39, 38, 65,
    76, 45, 22, 21, 20, 19, 18, 37, 64,
    77, 46, 23,  8,  7,  6, 17, 36, 63,
    78, 47, 24,  9,  1,  5, 16, 35, 62,
    79, 48, 25,  2,  3,  4, 15, 34, 61,
    80, 49, 10, 11, 12, 13, 14, 33, 60,
    81, 26, 27, 28, 29, 30, 31, 32, 59,
    50, 51, 52, 53, 54, 55, 56, 57, 58
};

// ---------------- binomial blur + uint8 quantization -------------------------
// 1 row x 2 cols per thread; blockIdx.z selects image (0=cur, 1=prev).
__device__ __forceinline__ unsigned char quant8(float v) {
    return (unsigned char)fminf(fmaxf(rintf(v * 255.0f), 0.0f), 255.0f);
}

__global__ void __launch_bounds__(128) blur_kernel(const float* __restrict__ cur,
                                                   const float* __restrict__ prev) {
    const int lane = threadIdx.x;
    const int x2   = (blockIdx.x * 32 + lane) * 2;            // W = 15*64
    const int y    = blockIdx.y * 4 + threadIdx.y;            // H = 136*4
    const int im   = blockIdx.z;
    const float* __restrict__ img = im ? prev : cur;

    const int yu = max(y - 1, 0) * W;
    const int ym = y * W;
    const int yd = min(y + 1, H - 1) * W;

    float2 u = *(const float2*)&img[yu + x2];
    float2 m = *(const float2*)&img[ym + x2];
    float2 d = *(const float2*)&img[yd + x2];
    float v0 = (u.x + 2.0f * m.x + d.x) * 0.25f;
    float v1 = (u.y + 2.0f * m.y + d.y) * 0.25f;
    float vL = __shfl_up_sync(0xffffffffu, v1, 1);
    float vR = __shfl_down_sync(0xffffffffu, v0, 1);
    if (lane == 0) {
        int xl = max(x2 - 1, 0);
        vL = (img[yu + xl] + 2.0f * img[ym + xl] + img[yd + xl]) * 0.25f;
    }
    if (lane == 31) {
        int xr = min(x2 + 2, W - 1);
        vR = (img[yu + xr] + 2.0f * img[ym + xr] + img[yd + xr]) * 0.25f;
    }
    float o0 = (vL + 2.0f * v0 + v1) * 0.25f;
    float o1 = (v0 + 2.0f * v1 + vR) * 0.25f;
    if (im == 0) {
        *(float2*)&g_cur_blur[ym + x2] = make_float2(o0, o1);
        *(uchar2*)&g_cur_q[ym + x2]    = make_uchar2(quant8(o0), quant8(o1));
    } else {
        *(uchar2*)&g_prev_q[ym + x2]   = make_uchar2(quant8(o0), quant8(o1));
    }
    cudaTriggerProgrammaticLaunchCompletion();
}

// ---------------- SAD matching: warp per block, __vsadu4 SIMD ---------------
__global__ void __launch_bounds__(256) match_kernel() {
    __shared__ unsigned win[8][WIN][5];

    const int wid  = threadIdx.x >> 5;
    const int lane = threadIdx.x & 31;
    const int blk  = blockIdx.x * 8 + wid;       // NB = 1020*8 exactly
    const int by = blk / WB, bx = blk % WB;

    cudaGridDependencySynchronize();             // wait for blur results

    // ---- load 16x16 search window of prev_q (2 rows of 8B per lane) ----
    {
        const int wy  = lane >> 1;
        const int wx0 = (lane & 1) * 8;
        const bool interior = (by >= 1 && by <= HB - 2 && bx >= 1 && bx <= WB - 2);
        unsigned lo, hi;
        if (interior) {
            const unsigned char* p = g_prev_q + (by * T - R + wy) * W + bx * T - R + wx0;
            lo = *(const unsigned*)p;
            hi = *(const unsigned*)(p + 4);
        } else {
            lo = 0; hi = 0;
            int gy = min(max(by * T - R + wy, 0), H - 1);
#pragma unroll
            for (int b = 0; b < 4; b++) {
                int gx = min(max(bx * T - R + wx0 + b, 0), W - 1);
                lo |= (unsigned)g_prev_q[gy * W + gx] << (8 * b);
            }
#pragma unroll
            for (int b = 0; b < 4; b++) {
                int gx = min(max(bx * T - R + wx0 + 4 + b, 0), W - 1);
                hi |= (unsigned)g_prev_q[gy * W + gx] << (8 * b);
            }
        }
        win[wid][wy][wx0 >> 2]       = lo;
        win[wid][wy][(wx0 >> 2) + 1] = hi;
    }

    // ---- template rows in registers (broadcast loads, 8B aligned) ----
    unsigned tlo[T], thi[T];
#pragma unroll
    for (int ty = 0; ty < T; ty++) {
        uint2 t = *(const uint2*)(g_cur_q + (by * T + ty) * W + bx * T);
        tlo[ty] = t.x; thi[ty] = t.y;
    }
    __syncwarp();

    // ---- 81 candidates over 32 lanes (up to 3 each) ----
    unsigned key = 0xffffffffu;
#pragma unroll
    for (int j = 0; j < 3; j++) {
        int c = lane + j * 32;
        if (c < NC) {
            int cy = c / 9, cx = c - cy * 9;
            int k8 = (cx & 3) * 8, bw = cx >> 2;
            unsigned sad = 0;
#pragma unroll
            for (int ty = 0; ty < T; ty++) {
                const unsigned* row = &win[wid][ty + cy][0];
                unsigned w0 = row[bw], w1 = row[bw + 1], w2 = row[bw + 2];
                unsigned lo = __funnelshift_r(w0, w1, k8);
                unsigned hi = __funnelshift_r(w1, w2, k8);
                sad += __vsadu4(lo, tlo[ty]) + __vsadu4(hi, thi[ty]);
            }
            unsigned kk = ((sad * 128u + (unsigned)c_spiral[c]) << 7) | (unsigned)c;
            key = min(key, kk);
        }
    }
#pragma unroll
    for (int s = 16; s > 0; s >>= 1)
        key = min(key, __shfl_xor_sync(0xffffffffu, key, s));

    if (lane == 0) {
        int c  = key & 127;
        int dy = c / 9 - R;
        int dx = c % 9 - R;
        g_vec[blk] = make_char2((char)(-dy), (char)(-dx));
    }
    cudaTriggerProgrammaticLaunchCompletion();
}

// ---------------- packed byte-SIMD median of 9 (Paeth network) --------------
#define SWU(a,b) { unsigned _t = __vminu4(a,b); b = __vmaxu4(a,b); a = _t; }
__device__ __forceinline__ unsigned med9u(unsigned v0, unsigned v1, unsigned v2,
                                          unsigned v3, unsigned v4, unsigned v5,
                                          unsigned v6, unsigned v7, unsigned v8) {
    SWU(v1,v2) SWU(v4,v5) SWU(v7,v8)
    SWU(v0,v1) SWU(v3,v4) SWU(v6,v7)
    SWU(v1,v2) SWU(v4,v5) SWU(v7,v8)
    SWU(v0,v3) SWU(v5,v8) SWU(v4,v7)
    SWU(v3,v6) SWU(v1,v4) SWU(v2,v5)
    SWU(v4,v7) SWU(v4,v2) SWU(v6,v4)
    SWU(v4,v2)
    return v4;
}

// ---------------- median + LK subpixel + flow output (warp / block) ---------
__global__ void __launch_bounds__(256) flow_kernel(float* __restrict__ out) {
    const int wid  = threadIdx.x >> 5;
    const int lane = threadIdx.x & 31;
    const int blk  = blockIdx.x * 8 + wid;       // NB = 1020*8 exactly
    const int by = blk / WB, bx = blk % WB;

    // lane -> border pixel (28 border pixels of the 8x8 block)
    int ty, tx;
    bool act = lane < 28;
    if      (lane < 8)  { ty = 0;         tx = lane;      }
    else if (lane < 16) { ty = 7;         tx = lane - 8;  }
    else if (lane < 22) { ty = lane - 15; tx = 0;         }
    else                { ty = lane - 21; tx = 7;         }
    const int gy0 = by * T + ty, gx0 = bx * T + tx;

    cudaGridDependencySynchronize();             // wait for match results

    // lanes 0..8 load the 3x3 neighborhood; pack (vy+4) | (vx+4)<<8
    unsigned pk = 0;
    if (lane < 9) {
        int ny = min(max(by + lane / 3 - 1, 0), HB - 1);
        int nx = min(max(bx + lane % 3 - 1, 0), WB - 1);
        char2 v = g_vec[ny * WB + nx];
        pk = (unsigned)(v.x + 4) | ((unsigned)(v.y + 4) << 8);
    }
    unsigned a0 = __shfl_sync(0xffffffffu, pk, 0);
    unsigned a1 = __shfl_sync(0xffffffffu, pk, 1);
    unsigned a2 = __shfl_sync(0xffffffffu, pk, 2);
    unsigned a3 = __shfl_sync(0xffffffffu, pk, 3);
    unsigned a4 = __shfl_sync(0xffffffffu, pk, 4);
    unsigned a5 = __shfl_sync(0xffffffffu, pk, 5);
    unsigned a6 = __shfl_sync(0xffffffffu, pk, 6);
    unsigned a7 = __shfl_sync(0xffffffffu, pk, 7);
    unsigned a8 = __shfl_sync(0xffffffffu, pk, 8);
    unsigned md = med9u(a0,a1,a2,a3,a4,a5,a6,a7,a8);
    int medy = (int)(md & 0xff) - 4;
    int medx = (int)((md >> 8) & 0xff) - 4;
    int offy = -medy, offx = -medx;

    float a = 0.f, b = 0.f, d = 0.f, p = 0.f, q = 0.f;
    if (act) {
        float gyv = (g_cur_blur[min(gy0 + 1, H - 1) * W + gx0] -
                     g_cur_blur[max(gy0 - 1, 0)     * W + gx0]) * 0.5f;
        float gxv = (g_cur_blur[gy0 * W + min(gx0 + 1, W - 1)] -
                     g_cur_blur[gy0 * W + max(gx0 - 1, 0)]) * 0.5f;
        float tmpl = (float)g_cur_q[gy0 * W + gx0] * (1.0f / 255.0f);
        int my = min(max(gy0 + offy, 0), H - 1);
        int mx = min(max(gx0 + offx, 0), W - 1);
        float mat  = (float)g_prev_q[my * W + mx] * (1.0f / 255.0f);
        float diff = mat - tmpl;
        a = gxv * gxv;
        b = gxv * gyv;
        d = gyv * gyv;
        p = diff * gxv;
        q = diff * gyv;
    }
#pragma unroll
    for (int s = 16; s > 0; s >>= 1) {
        a += __shfl_xor_sync(0xffffffffu, a, s);
        b += __shfl_xor_sync(0xffffffffu, b, s);
        d += __shfl_xor_sync(0xffffffffu, d, s);
        p += __shfl_xor_sync(0xffffffffu, p, s);
        q += __shfl_xor_sync(0xffffffffu, q, s);
    }
    if (lane == 0) {
        float det = a * d - b * b;
        bool  bad = (det <= 1e-6f);
        float sd  = bad ? 1.0f : det;
        float su  = (d * p - b * q) / sd;
        float sv  = (a * q - b * p) / sd;
        float subv = (bad || fabsf(sv) >= 1.0f) ? 0.0f : sv;
        float subu = (bad || fabsf(su) >= 1.0f) ? 0.0f : su;
        out[blk]      = (float)medy + subv;
        out[NB + blk] = (float)medx + subu;
    }
}

// ---------------- entry point ------------------------------------------------
extern "C" void kernel_launch(void* const* d_in, const int* in_sizes, int n_in,
                              void* d_out, int out_size) {
    const float* cur  = (const float*)d_in[0];
    const float* prev = (const float*)d_in[1];
    float* out = (float*)d_out;

    // blur: plain launch, one image per blockIdx.z
    {
        dim3 bt(32, 4);
        dim3 bg(W / 64, H / 4, 2);       // 15 x 136 x 2 = 4080 blocks
        blur_kernel<<<bg, bt>>>(cur, prev);
    }

    // match + flow: programmatic dependent launches (overlap launch latency)
    cudaLaunchAttribute attr[1];
    attr[0].id = cudaLaunchAttributeProgrammaticStreamSerialization;
    attr[0].val.programmaticStreamSerializationAllowed = 1;

    {
        cudaLaunchConfig_t cfg = {};
        cfg.gridDim  = dim3(NB / 8, 1, 1);
        cfg.blockDim = dim3(256, 1, 1);
        cfg.dynamicSmemBytes = 0;
        cfg.stream = 0;
        cfg.attrs = attr;
        cfg.numAttrs = 1;
        cudaLaunchKernelEx(&cfg, match_kernel);
    }
    {
        cudaLaunchConfig_t cfg = {};
        cfg.gridDim  = dim3(NB / 8, 1, 1);
        cfg.blockDim = dim3(256, 1, 1);
        cfg.dynamicSmemBytes = 0;
        cfg.stream = 0;
        cfg.attrs = attr;
        cfg.numAttrs = 1;
        cudaLaunchKernelEx(&cfg, flow_kernel, out);
    }
}

// round 6
// speedup vs baseline: 1.0960x; 1.0960x over previous
#include <cuda_runtime.h>

// Problem constants (fixed by setup_inputs: img [1,1,544,960], T=8, R=4)
#define H  544
#define W  960
#define T  8
#define R  4
#define HB (H/T)                  // 68
#define WB (W/T)                  // 120
#define NB (HB*WB)                // 8160
#define NC ((2*R+1)*(2*R+1))      // 81

// ---------------- scratch (device globals) ----------------------------------
__device__ float         g_cur_blur[H*W];
__device__ unsigned char g_cur_q[H*W];
__device__ unsigned char g_prev_q[H*W];
__device__ char2         g_vec[NB];     // (vy, vx) = (-dy, -dx)

// spiral rank LUT (row-major over (dy+R, dx+R)), precomputed for R=4
__constant__ unsigned char c_spiral[NC] = {
    74, 73, 72, 71, 70, 69, 68, 67, 66,
    75, 44, 43, 42, 41, 40, 39, 38, 65,
    76, 45, 22, 21, 20, 19, 18, 37, 64,
    77, 46, 23,  8,  7,  6, 17, 36, 63,
    78, 47, 24,  9,  1,  5, 16, 35, 62,
    79, 48, 25,  2,  3,  4, 15, 34, 61,
    80, 49, 10, 11, 12, 13, 14, 33, 60,
    81, 26, 27, 28, 29, 30, 31, 32, 59,
    50, 51, 52, 53, 54, 55, 56, 57, 58
};

__device__ __forceinline__ unsigned char quant8(float v) {
    return (unsigned char)fminf(fmaxf(rintf(v * 255.0f), 0.0f), 255.0f);
}
__device__ __forceinline__ int clampi(int v, int lo, int hi) {
    return min(max(v, lo), hi);
}

// ================= fused blur + quantize + SAD match =========================
// One CTA (256 thr) owns a 64x8 strip = 8 template blocks (warp per block).
// Blur computed locally in smem (separable, replicate-clamped at the BLURRED
// image level via clamp-indexed h/v passes, matching blur-then-pad semantics).
__global__ void __launch_bounds__(256) fused_match_kernel(const float* __restrict__ cur,
                                                          const float* __restrict__ prev) {
    __shared__ float    rawA[18][76];   // raw pixels (prev: 18x74, cur: 10x66)
    __shared__ float    vbuf[16][76];   // vertical-pass values
    __shared__ unsigned winw[16][20];   // blurred+quantized prev window, 72B/row (+pad)
    __shared__ unsigned tmplw[8][16];   // blurred+quantized cur strip, 64B/row

    const int tid = threadIdx.x;
    const int sx  = blockIdx.x;        // 0..14
    const int sy  = blockIdx.y;        // 0..67
    const int x0  = sx * 64;
    const int y0  = sy * 8;

    // ---- S0: load raw prev (18 rows x 74 cols), coords clamped ----
    for (int i = tid; i < 18 * 74; i += 256) {
        int ry = i / 74, rx = i - ry * 74;
        int gy = clampi(y0 - 5 + ry, 0, H - 1);
        int gx = clampi(x0 - 5 + rx, 0, W - 1);
        rawA[ry][rx] = prev[gy * W + gx];
    }
    __syncthreads();

    // ---- S1: vertical pass prev at clamp(image row) ----
    for (int i = tid; i < 16 * 74; i += 256) {
        int wy = i / 74, rx = i - wy * 74;
        int rr = clampi(y0 - 4 + wy, 0, H - 1);
        int j1 = rr - (y0 - 5);                        // in [1,17]
        vbuf[wy][rx] = (rawA[j1-1][rx] + 2.0f * rawA[j1][rx] + rawA[j1+1][rx]) * 0.25f;
    }
    __syncthreads();

    // ---- S2: horizontal pass prev at clamp(image col) + owned prev_q store;
    //          concurrently load raw cur (10 x 66) into rawA ----
    for (int i = tid; i < 16 * 72; i += 256) {
        int wy = i / 72, wx = i - wy * 72;
        int cc = clampi(x0 - 4 + wx, 0, W - 1);
        int i1 = cc - (x0 - 5);                        // in [1,73]
        float o = (vbuf[wy][i1-1] + 2.0f * vbuf[wy][i1] + vbuf[wy][i1+1]) * 0.25f;
        unsigned char qv = quant8(o);
        ((unsigned char*)&winw[wy][0])[wx] = qv;
        if (wy >= 4 && wy < 12 && wx >= 4 && wx < 68)
            g_prev_q[(y0 + wy - 4) * W + (x0 + wx - 4)] = qv;
    }
    for (int i = tid; i < 10 * 66; i += 256) {
        int ry = i / 66, rx = i - ry * 66;
        int gy = clampi(y0 - 1 + ry, 0, H - 1);
        int gx = clampi(x0 - 1 + rx, 0, W - 1);
        rawA[ry][rx] = cur[gy * W + gx];
    }
    __syncthreads();

    // ---- S3: vertical pass cur (all owned rows are in-image; halo clamp
    //          is handled by the clamped raw load) ----
    for (int i = tid; i < 8 * 66; i += 256) {
        int ty = i / 66, rx = i - ty * 66;
        vbuf[ty][rx] = (rawA[ty][rx] + 2.0f * rawA[ty+1][rx] + rawA[ty+2][rx]) * 0.25f;
    }
    __syncthreads();

    // ---- S4: horizontal pass cur + stores (cur_blur, cur_q, smem template) ----
    for (int i = tid; i < 8 * 64; i += 256) {
        int ty = i >> 6, txx = i & 63;
        float o = (vbuf[ty][txx] + 2.0f * vbuf[ty][txx+1] + vbuf[ty][txx+2]) * 0.25f;
        int g = (y0 + ty) * W + x0 + txx;
        g_cur_blur[g] = o;
        unsigned char qv = quant8(o);
        ((unsigned char*)&tmplw[ty][0])[txx] = qv;
        g_cur_q[g] = qv;
    }
    __syncthreads();

    // ---- S5: SAD over 81 candidates; warp wid handles block bx = sx*8+wid ----
    const int wid  = tid >> 5;
    const int lane = tid & 31;

    unsigned tlo[T], thi[T];
#pragma unroll
    for (int ty = 0; ty < T; ty++) {
        tlo[ty] = tmplw[ty][wid * 2];
        thi[ty] = tmplw[ty][wid * 2 + 1];
    }

    unsigned key = 0xffffffffu;
#pragma unroll
    for (int j = 0; j < 3; j++) {
        int c = lane + j * 32;
        if (c < NC) {
            int cy = c / 9, cx = c - cy * 9;
            int sb = wid * 8 + cx;                 // start byte within 72B row
            int k8 = (sb & 3) * 8, bw = sb >> 2;
            unsigned sad = 0;
#pragma unroll
            for (int ty = 0; ty < T; ty++) {
                const unsigned* row = &winw[ty + cy][0];
                unsigned w0 = row[bw], w1 = row[bw + 1], w2 = row[bw + 2];
                unsigned lo = __funnelshift_r(w0, w1, k8);
                unsigned hi = __funnelshift_r(w1, w2, k8);
                sad += __vsadu4(lo, tlo[ty]) + __vsadu4(hi, thi[ty]);
            }
            unsigned kk = ((sad * 128u + (unsigned)c_spiral[c]) << 7) | (unsigned)c;
            key = min(key, kk);
        }
    }
#pragma unroll
    for (int s = 16; s > 0; s >>= 1)
        key = min(key, __shfl_xor_sync(0xffffffffu, key, s));

    if (lane == 0) {
        int c  = key & 127;
        int dy = c / 9 - R;
        int dx = c % 9 - R;
        g_vec[sy * WB + sx * 8 + wid] = make_char2((char)(-dy), (char)(-dx));
    }
    cudaTriggerProgrammaticLaunchCompletion();
}

// ---------------- packed byte-SIMD median of 9 (Paeth network) --------------
#define SWU(a,b) { unsigned _t = __vminu4(a,b); b = __vmaxu4(a,b); a = _t; }
__device__ __forceinline__ unsigned med9u(unsigned v0, unsigned v1, unsigned v2,
                                          unsigned v3, unsigned v4, unsigned v5,
                                          unsigned v6, unsigned v7, unsigned v8) {
    SWU(v1,v2) SWU(v4,v5) SWU(v7,v8)
    SWU(v0,v1) SWU(v3,v4) SWU(v6,v7)
    SWU(v1,v2) SWU(v4,v5) SWU(v7,v8)
    SWU(v0,v3) SWU(v5,v8) SWU(v4,v7)
    SWU(v3,v6) SWU(v1,v4) SWU(v2,v5)
    SWU(v4,v7) SWU(v4,v2) SWU(v6,v4)
    SWU(v4,v2)
    return v4;
}

// ---------------- median + LK subpixel + flow output (warp / block) ---------
__global__ void __launch_bounds__(256) flow_kernel(float* __restrict__ out) {
    const int wid  = threadIdx.x >> 5;
    const int lane = threadIdx.x & 31;
    const int blk  = blockIdx.x * 8 + wid;       // NB = 1020*8 exactly
    const int by = blk / WB, bx = blk % WB;

    // lane -> border pixel (28 border pixels of the 8x8 block)
    int ty, tx;
    bool act = lane < 28;
    if      (lane < 8)  { ty = 0;         tx = lane;      }
    else if (lane < 16) { ty = 7;         tx = lane - 8;  }
    else if (lane < 22) { ty = lane - 15; tx = 0;         }
    else                { ty = lane - 21; tx = 7;         }
    const int gy0 = by * T + ty, gx0 = bx * T + tx;

    cudaGridDependencySynchronize();             // wait for fused_match results

    // lanes 0..8 load the 3x3 neighborhood; pack (vy+4) | (vx+4)<<8
    unsigned pk = 0;
    if (lane < 9) {
        int ny = clampi(by + lane / 3 - 1, 0, HB - 1);
        int nx = clampi(bx + lane % 3 - 1, 0, WB - 1);
        char2 v = g_vec[ny * WB + nx];
        pk = (unsigned)(v.x + 4) | ((unsigned)(v.y + 4) << 8);
    }
    unsigned a0 = __shfl_sync(0xffffffffu, pk, 0);
    unsigned a1 = __shfl_sync(0xffffffffu, pk, 1);
    unsigned a2 = __shfl_sync(0xffffffffu, pk, 2);
    unsigned a3 = __shfl_sync(0xffffffffu, pk, 3);
    unsigned a4 = __shfl_sync(0xffffffffu, pk, 4);
    unsigned a5 = __shfl_sync(0xffffffffu, pk, 5);
    unsigned a6 = __shfl_sync(0xffffffffu, pk, 6);
    unsigned a7 = __shfl_sync(0xffffffffu, pk, 7);
    unsigned a8 = __shfl_sync(0xffffffffu, pk, 8);
    unsigned md = med9u(a0,a1,a2,a3,a4,a5,a6,a7,a8);
    int medy = (int)(md & 0xff) - 4;
    int medx = (int)((md >> 8) & 0xff) - 4;
    int offy = -medy, offx = -medx;

    float a = 0.f, b = 0.f, d = 0.f, p = 0.f, q = 0.f;
    if (act) {
        float gyv = (g_cur_blur[min(gy0 + 1, H - 1) * W + gx0] -
                     g_cur_blur[max(gy0 - 1, 0)     * W + gx0]) * 0.5f;
        float gxv = (g_cur_blur[gy0 * W + min(gx0 + 1, W - 1)] -
                     g_cur_blur[gy0 * W + max(gx0 - 1, 0)]) * 0.5f;
        float tmpl = (float)g_cur_q[gy0 * W + gx0] * (1.0f / 255.0f);
        int my = clampi(gy0 + offy, 0, H - 1);
        int mx = clampi(gx0 + offx, 0, W - 1);
        float mat  = (float)g_prev_q[my * W + mx] * (1.0f / 255.0f);
        float diff = mat - tmpl;
        a = gxv * gxv;
        b = gxv * gyv;
        d = gyv * gyv;
        p = diff * gxv;
        q = diff * gyv;
    }
#pragma unroll
    for (int s = 16; s > 0; s >>= 1) {
        a += __shfl_xor_sync(0xffffffffu, a, s);
        b += __shfl_xor_sync(0xffffffffu, b, s);
        d += __shfl_xor_sync(0xffffffffu, d, s);
        p += __shfl_xor_sync(0xffffffffu, p, s);
        q += __shfl_xor_sync(0xffffffffu, q, s);
    }
    if (lane == 0) {
        float det = a * d - b * b;
        bool  bad = (det <= 1e-6f);
        float sd  = bad ? 1.0f : det;
        float su  = (d * p - b * q) / sd;
        float sv  = (a * q - b * p) / sd;
        float subv = (bad || fabsf(sv) >= 1.0f) ? 0.0f : sv;
        float subu = (bad || fabsf(su) >= 1.0f) ? 0.0f : su;
        out[blk]      = (float)medy + subv;
        out[NB + blk] = (float)medx + subu;
    }
}

// ---------------- entry point ------------------------------------------------
extern "C" void kernel_launch(void* const* d_in, const int* in_sizes, int n_in,
                              void* d_out, int out_size) {
    const float* cur  = (const float*)d_in[0];
    const float* prev = (const float*)d_in[1];
    float* out = (float*)d_out;

    // fused blur + match: one CTA per 64x8 strip
    {
        dim3 bg(15, 68);
        fused_match_kernel<<<bg, 256>>>(cur, prev);
    }

    // flow: programmatic dependent launch (overlap launch latency)
    cudaLaunchAttribute attr[1];
    attr[0].id = cudaLaunchAttributeProgrammaticStreamSerialization;
    attr[0].val.programmaticStreamSerializationAllowed = 1;
    {
        cudaLaunchConfig_t cfg = {};
        cfg.gridDim  = dim3(NB / 8, 1, 1);
        cfg.blockDim = dim3(256, 1, 1);
        cfg.dynamicSmemBytes = 0;
        cfg.stream = 0;
        cfg.attrs = attr;
        cfg.numAttrs = 1;
        cudaLaunchKernelEx(&cfg, flow_kernel, out);
    }
}